// round 10
// baseline (speedup 1.0000x reference)
#include <cuda_runtime.h>
#include <math.h>

// SDF2: mesh -> voxel (inside ? distance : 0) grid. Round-10:
//   - round-7 skeleton (balanced chunks, K=16 incremental, hoisted parity,
//     atomic reduce); round-9 cull REMOVED (never fired: box too big vs plane)
//   - NEW: warp-uniform Ericson-region fast paths. All region predicates
//     (d1..d6, vb, vc, va=gram-vb-vc, d43, d56) are affine in z -> endpoint
//     tests + warp vote decide "entire 512-pt warp box in one region":
//       vertex region: d^2 = cxy + rz^2            (2 fma-ops/k vs 31)
//       edge region:   r += const Delta-r, |r|^2   (6/k, cancellation-free)
//       interior:      hh = hs^2, hs += ihs        (2/k)
//     strict inequalities => fp-boundary cases fall back to the full loop;
//     degenerate faces never pass the strict tests (exact zeros).

#define G_DIM    32
#define N_PTS    (G_DIM * G_DIM * G_DIM)          // 32768
#define N_FACES  2048
#define N_CHUNKS 37
#define TRI_MAX  56
#define KPT      16
#define N_GROUPS (N_PTS / KPT)                    // 2048
#define THREADS  128
#define EPSF     1e-12f

__device__ unsigned g_md2min[N_PTS];              // float bits, monotone (md2>=0)
__device__ unsigned g_parity[N_GROUPS];           // 16 parity bits per word

__global__ void __launch_bounds__(256)
sdf_init()
{
    int i = blockIdx.x * 256 + threadIdx.x;
    if (i < N_PTS)    g_md2min[i] = 0x7F800000u;  // +inf
    if (i < N_GROUPS) g_parity[i] = 0u;
}

__global__ void __launch_bounds__(THREADS, 4)
sdf_main(const int* __restrict__ faces, const float* __restrict__ verts)
{
    // 12 float4 per triangle:
    // 0: ab.xyz, inv_ab    1: ac.xyz, inv_ac    2: bc.xyz, inv_bc
    // 3: A.xyz, qaa        4: B.xyz, qab        5: C.xyz, qac
    // 6: n.xyz, gram       7: iab, iac, ihs, inv_n
    // 8: 15iab, 15iac, 15ivb, 15ivc
    // 9: dAB.xyz, ivb     10: dAC.xyz, ivc     11: dBC.xyz, 0
    __shared__ float4 tc[12 * TRI_MAX];           // 10.5 KB

    const int start = (blockIdx.y * N_FACES) / N_CHUNKS;
    const int end   = ((blockIdx.y + 1) * N_FACES) / N_CHUNKS;
    const int ntri  = end - start;
    const float dz  = 1.0f / (float)G_DIM;

    if (threadIdx.x < ntri) {
        const int f = threadIdx.x;
        const int base = (start + f) * 3;
        const float* va  = verts + 3 * faces[base + 0];
        const float* vbv = verts + 3 * faces[base + 1];
        const float* vcv = verts + 3 * faces[base + 2];
        float Ax = va[0],  Ay = va[1],  Az = va[2];
        float Bx = vbv[0], By = vbv[1], Bz = vbv[2];
        float Cx = vcv[0], Cy = vcv[1], Cz = vcv[2];

        float abx = Bx - Ax, aby = By - Ay, abz = Bz - Az;
        float acx = Cx - Ax, acy = Cy - Ay, acz = Cz - Az;
        float bcx = Cx - Bx, bcy = Cy - By, bcz = Cz - Bz;

        float qaa = abx * abx + aby * aby + abz * abz;
        float qab = abx * acx + aby * acy + abz * acz;
        float qac = acx * acx + acy * acy + acz * acz;
        float qbc = bcx * bcx + bcy * bcy + bcz * bcz;

        float nx = aby * acz - abz * acy;
        float ny = abz * acx - abx * acz;
        float nz = abx * acy - aby * acx;
        float gram = nx * nx + ny * ny + nz * nz;

        float inv_ab = __fdividef(1.0f, fmaxf(qaa, EPSF));
        float inv_ac = __fdividef(1.0f, fmaxf(qac, EPSF));
        float inv_bc = __fdividef(1.0f, fmaxf(qbc, EPSF));
        float inv_n  = rsqrtf(fmaxf(gram, EPSF));

        float iab = abz * dz, iac = acz * dz, i43 = iac - iab;
        float ivb = (qac * abz - qab * acz) * dz;
        float ivc = (qaa * acz - qab * abz) * dz;
        float ihs = nz * dz * inv_n;

        float tAB = iab * inv_ab, tAC = iac * inv_ac, tBC = i43 * inv_bc;

        tc[12 * f + 0]  = make_float4(abx, aby, abz, inv_ab);
        tc[12 * f + 1]  = make_float4(acx, acy, acz, inv_ac);
        tc[12 * f + 2]  = make_float4(bcx, bcy, bcz, inv_bc);
        tc[12 * f + 3]  = make_float4(Ax, Ay, Az, qaa);
        tc[12 * f + 4]  = make_float4(Bx, By, Bz, qab);
        tc[12 * f + 5]  = make_float4(Cx, Cy, Cz, qac);
        tc[12 * f + 6]  = make_float4(nx, ny, nz, gram);
        tc[12 * f + 7]  = make_float4(iab, iac, ihs, inv_n);
        tc[12 * f + 8]  = make_float4(15.0f * iab, 15.0f * iac, 15.0f * ivb, 15.0f * ivc);
        tc[12 * f + 9]  = make_float4(-tAB * abx, -tAB * aby, dz - tAB * abz, ivb);
        tc[12 * f + 10] = make_float4(-tAC * acx, -tAC * acy, dz - tAC * acz, ivc);
        tc[12 * f + 11] = make_float4(-tBC * bcx, -tBC * bcy, dz - tBC * bcz, 0.0f);
    }
    __syncthreads();

    // warp-compact mapping: warp covers 4(ix) x 8(iy) x one z-half
    const int w  = threadIdx.x >> 5, l = threadIdx.x & 31;
    const int bx = blockIdx.x;                            // [0,16)
    const int ix = ((bx >> 2) << 3) + ((w >> 1) << 2) + (l >> 3);
    const int iy = ((bx & 3) << 3) + (l & 7);
    const int zh = w & 1;
    const int iz0 = zh << 4;

    const float px  = ((float)ix  + 0.5f) * dz;
    const float py  = ((float)iy  + 0.5f) * dz;
    const float pz0 = ((float)iz0 + 0.5f) * dz;
    const int pbase = ((ix * 32 + iy) * 32) + iz0;
    const int gidx  = (ix * 32 + iy) * 2 + zh;

    float md[KPT];
    #pragma unroll
    for (int k = 0; k < KPT; ++k) md[k] = INFINITY;
    unsigned par = 0u;

    for (int f = 0; f < ntri; ++f) {
        const float4 c3 = tc[12 * f + 3];
        const float4 c4 = tc[12 * f + 4];
        const float4 c5 = tc[12 * f + 5];
        const float4 c6 = tc[12 * f + 6];
        const float4 c7 = tc[12 * f + 7];
        const float4 c8 = tc[12 * f + 8];
        const float qaa = c3.w, qab = c4.w, qac = c5.w, gram = c6.w;

        // ---- ray crossing (den == nz), fully hoisted ----
        {
            float cpx2 = px - c5.x, cpy2 = py - c5.y;
            float nz = c6.z;
            float e0 = c4.y - c5.y;
            float e1 = c5.x - c4.x;
            float un = e0 * cpx2 + e1 * cpy2;
            float vn = (c5.y - c3.y) * cpx2 + (c3.x - c5.x) * cpy2;
            float wn = nz - un - vn;
            bool c2d = (fabsf(nz) >= EPSF)
                     & (un * nz >= 0.0f) & (vn * nz >= 0.0f) & (wn * nz >= 0.0f);
            if (c2d) {
                float zhit = __fdividef(un * c3.z + vn * c4.z + wn * c5.z, nz);
                float fcnt = (zhit - pz0) * (float)G_DIM;
                int n = (int)ceilf(fminf(fmaxf(fcnt, 0.0f), (float)KPT));
                par ^= (1u << n) - 1u;
            }
        }

        const float4 c0 = tc[12 * f + 0];
        const float4 c1 = tc[12 * f + 1];

        const float apx = px - c3.x, apy = py - c3.y;
        const float apz0 = pz0 - c3.z;
        float d1_0 = c0.x * apx + c0.y * apy + c0.z * apz0;   // ab.ap at k=0
        float d2_0 = c1.x * apx + c1.y * apy + c1.z * apz0;   // ac.ap
        float d1_E = d1_0 + c8.x;                             // at k=15
        float d2_E = d2_0 + c8.y;

        float d3_0 = d1_0 - qaa, d3_E = d1_E - qaa;
        float d4_0 = d2_0 - qab, d4_E = d2_E - qab;
        float d5_0 = d1_0 - qab, d5_E = d1_E - qab;
        float d6_0 = d2_0 - qac, d6_E = d2_E - qac;
        float vb_0 = qac * d1_0 - qab * d2_0, vb_E = vb_0 + c8.z;
        float vc_0 = qaa * d2_0 - qab * d1_0, vc_E = vc_0 + c8.w;
        float va_0 = gram - vb_0 - vc_0,      va_E = gram - vb_E - vc_E;
        float d43_0 = d4_0 - d3_0, d43_E = d4_E - d3_E;
        float d56_0 = d5_0 - d6_0, d56_E = d5_E - d6_E;

        // region id: strict membership at BOTH endpoints (affine => all k)
        bool inA = (d1_0 < 0.0f) & (d2_0 < 0.0f) & (d1_E < 0.0f) & (d2_E < 0.0f);
        bool inB = (d3_0 > 0.0f) & (d4_0 < d3_0) & (d3_E > 0.0f) & (d4_E < d3_E);
        bool inC = (d6_0 > 0.0f) & (d5_0 < d6_0) & (d6_E > 0.0f) & (d5_E < d6_E);
        bool eAB = (vc_0 < 0.0f) & (d1_0 > 0.0f) & (d3_0 < 0.0f)
                 & (vc_E < 0.0f) & (d1_E > 0.0f) & (d3_E < 0.0f);
        bool eAC = (vb_0 < 0.0f) & (d2_0 > 0.0f) & (d6_0 < 0.0f)
                 & (vb_E < 0.0f) & (d2_E > 0.0f) & (d6_E < 0.0f);
        bool eBC = (va_0 < 0.0f) & (d43_0 > 0.0f) & (d56_0 > 0.0f)
                 & (va_E < 0.0f) & (d43_E > 0.0f) & (d56_E > 0.0f);
        bool inT = (va_0 > 0.0f) & (vb_0 > 0.0f) & (vc_0 > 0.0f)
                 & (va_E > 0.0f) & (vb_E > 0.0f) & (vc_E > 0.0f);

        int id = 7;
        if (inT) id = 6;
        if (eBC) id = 5;
        if (eAC) id = 4;
        if (eAB) id = 3;
        if (inC) id = 2;
        if (inB) id = 1;
        if (inA) id = 0;

        int id0 = __shfl_sync(0xFFFFFFFFu, id, 0);
        bool uni = __all_sync(0xFFFFFFFFu, id == id0);

        if (uni && id0 <= 2) {
            // ---- whole warp box closest to ONE vertex ----
            float4 V = (id0 == 0) ? c3 : (id0 == 1) ? c4 : c5;
            float vx = px - V.x, vy = py - V.y;
            float cxy = vx * vx + vy * vy;
            float rz = pz0 - V.z;
            #pragma unroll
            for (int k = 0; k < KPT; ++k) {
                float d = fmaf(rz, rz, cxy);
                md[k] = fminf(md[k], d);
                rz += dz;
            }
        } else if (uni && id0 <= 5) {
            // ---- whole warp box closest to ONE edge (interior of segment) ----
            const float4 c9  = tc[12 * f + 9];
            const float4 c10 = tc[12 * f + 10];
            const float4 c11 = tc[12 * f + 11];
            float4 E = (id0 == 3) ? c0 : (id0 == 4) ? c1 : tc[12 * f + 2];
            float4 D = (id0 == 3) ? c9 : (id0 == 4) ? c10 : c11;
            float4 P = (id0 == 5) ? c4 : c3;                   // base vertex
            float dv = (id0 == 3) ? d1_0 : (id0 == 4) ? d2_0 : d43_0;
            float t0 = dv * E.w;
            float rx = (px - P.x) - t0 * E.x;
            float ry = (py - P.y) - t0 * E.y;
            float rz = (pz0 - P.z) - t0 * E.z;
            #pragma unroll
            for (int k = 0; k < KPT; ++k) {
                float d = rx * rx;
                d = fmaf(ry, ry, d);
                d = fmaf(rz, rz, d);
                md[k] = fminf(md[k], d);
                rx += D.x; ry += D.y; rz += D.z;
            }
        } else if (uni && id0 == 6) {
            // ---- whole warp box projects inside: plane distance ----
            float hs = (c6.x * apx + c6.y * apy + c6.z * apz0) * c7.w;
            float ihs = c7.z;
            #pragma unroll
            for (int k = 0; k < KPT; ++k) {
                float d = hs * hs;
                md[k] = fminf(md[k], d);
                hs += ihs;
            }
        } else {
            // ---- mixed: full round-7 body ----
            const float4 c2 = tc[12 * f + 2];
            const float ivb = tc[12 * f + 9].w;
            const float ivc = tc[12 * f + 10].w;
            const float bpx = px - c4.x, bpy = py - c4.y;
            float apz = apz0;
            float bpz = pz0 - c4.z;
            float d1 = d1_0, d2 = d2_0, d43 = d43_0;
            float vb = vb_0, vc = vc_0;
            float hs = (c6.x * apx + c6.y * apy + c6.z * apz0) * c7.w;
            const float iab = c7.x, iac = c7.y, i43 = iac - iab, ihs = c7.z;

            #pragma unroll
            for (int k = 0; k < KPT; ++k) {
                float t1 = __saturatef(d1 * c0.w);
                float rx = apx - t1 * c0.x;
                float ry = apy - t1 * c0.y;
                float rz = apz - t1 * c0.z;
                float dAB = rx * rx + ry * ry + rz * rz;
                float t2 = __saturatef(d2 * c1.w);
                rx = apx - t2 * c1.x;
                ry = apy - t2 * c1.y;
                rz = apz - t2 * c1.z;
                float dAC = rx * rx + ry * ry + rz * rz;
                float t3 = __saturatef(d43 * c2.w);
                rx = bpx - t3 * c2.x;
                ry = bpy - t3 * c2.y;
                rz = bpz - t3 * c2.z;
                float dBC = rx * rx + ry * ry + rz * rz;

                float m = fminf(fminf(dAB, dAC), dBC);

                float s = vb + vc;
                bool inter = (vb > 0.0f) & (vc > 0.0f) & (s < gram);
                float hh = hs * hs;
                m = inter ? hh : m;

                md[k] = fminf(md[k], m);

                d1 += iab; d2 += iac; d43 += i43;
                apz += dz; bpz += dz;
                hs += ihs; vb += ivb; vc += ivc;
            }
        }
    }

    #pragma unroll
    for (int k = 0; k < KPT; ++k)
        atomicMin(&g_md2min[pbase + k], __float_as_uint(md[k]));
    if (par) atomicXor(&g_parity[gidx], par);
}

__global__ void __launch_bounds__(256)
sdf_finalize(float* __restrict__ out)
{
    int p = blockIdx.x * 256 + threadIdx.x;               // [0, 32768)
    float m = __uint_as_float(g_md2min[p]);
    int gidx = (p >> 5) * 2 + ((p >> 4) & 1);
    unsigned par = (g_parity[gidx] >> (p & 15)) & 1u;
    out[p] = par ? sqrtf(m) : 0.0f;
}

extern "C" void kernel_launch(void* const* d_in, const int* in_sizes, int n_in,
                              void* d_out, int out_size)
{
    const int* faces = nullptr;
    const float* verts = nullptr;
    for (int i = 0; i < n_in; ++i) {
        if (in_sizes[i] == 3 * N_FACES)   faces = (const int*)d_in[i];
        else if (in_sizes[i] == 3 * 1026) verts = (const float*)d_in[i];
    }
    if (!faces) faces = (const int*)d_in[0];
    if (!verts) verts = (const float*)d_in[1];

    sdf_init<<<N_PTS / 256, 256>>>();
    dim3 grid(16, N_CHUNKS);                              // 592 blocks
    sdf_main<<<grid, THREADS>>>(faces, verts);
    sdf_finalize<<<N_PTS / 256, 256>>>((float*)d_out);
}

// round 11
// speedup vs baseline: 1.2478x; 1.2478x over previous
#include <cuda_runtime.h>
#include <math.h>

// SDF2: mesh -> voxel (inside ? distance : 0) grid. Round-11:
//   - round-7 body (known 102.6us); geometric warp-skips abandoned (2 failures:
//     sliver triangles' regions always cross warp-size boxes)
//   - KPT=32: one thread per (x,y) z-column -> per-pair setup amortized /32
//   - interior test interval-ized: vb,vc,va affine in k -> precompute the
//     k-interval where all three > 0 (per-pair: 3 muls + selects, steps'
//     reciprocals from staging), one 32-bit mask; per-k test = bit test (alu).
//     Removes vb/vc/s fma-adds (31 -> 28 fma-ops/k). Boundary-k misclass is
//     benign: interior and edge distances coincide at region boundaries.
//   - 592 blocks = 148 SMs x 4 (128 thr), 74 balanced chunks (27-28 tri)
//   - RED atomics reduce (atomicMin float bits, atomicXor 32-bit parity)

#define G_DIM    32
#define N_PTS    (G_DIM * G_DIM * G_DIM)          // 32768
#define N_FACES  2048
#define N_CHUNKS 74
#define TRI_MAX  28
#define KPT      32
#define N_GROUPS (N_PTS / KPT)                    // 1024
#define THREADS  128
#define EPSF     1e-12f
#define INF_F    __int_as_float(0x7F800000)

__device__ unsigned g_md2min[N_PTS];              // float bits, monotone (md2>=0)
__device__ unsigned g_parity[N_GROUPS];           // 32 parity bits per word

__global__ void __launch_bounds__(256)
sdf_init()
{
    int i = blockIdx.x * 256 + threadIdx.x;
    if (i < N_PTS)    g_md2min[i] = 0x7F800000u;  // +inf
    if (i < N_GROUPS) g_parity[i] = 0u;
}

// interval of k where L0 + k*i > 0 (strict); inv_i = 1/i precomputed (per-tri)
__device__ __forceinline__ void lin_interval(float L0, float i, float inv_i,
                                             float& lo, float& hi)
{
    float kl = -L0 * inv_i;
    if (i > 0.0f)      { lo = kl;     hi = INF_F; }
    else if (i < 0.0f) { lo = -INF_F; hi = kl; }
    else               { lo = (L0 > 0.0f) ? -INF_F : INF_F;
                         hi = (L0 > 0.0f) ?  INF_F : -INF_F; }
}

__global__ void __launch_bounds__(THREADS, 4)
sdf_main(const int* __restrict__ faces, const float* __restrict__ verts)
{
    // 10 float4 per triangle:
    // 0: ab.xyz, inv_ab   1: ac.xyz, inv_ac   2: bc.xyz, inv_bc
    // 3: A.xyz, kbc       4: B.xyz, inv_n     5: C.xyz, gram
    // 6: n.xyz, qab       7: qaa, qac, ivb, ivc
    // 8: iab, iac, ihs, iva   9: inv_ivb, inv_ivc, inv_iva, 0
    __shared__ float4 tc[10 * TRI_MAX];           // 4.5 KB

    const int start = (blockIdx.y * N_FACES) / N_CHUNKS;
    const int end   = ((blockIdx.y + 1) * N_FACES) / N_CHUNKS;
    const int ntri  = end - start;
    const float dz  = 1.0f / (float)G_DIM;

    if (threadIdx.x < ntri) {
        const int f = threadIdx.x;
        const int base = (start + f) * 3;
        const float* va  = verts + 3 * faces[base + 0];
        const float* vbv = verts + 3 * faces[base + 1];
        const float* vcv = verts + 3 * faces[base + 2];
        float Ax = va[0],  Ay = va[1],  Az = va[2];
        float Bx = vbv[0], By = vbv[1], Bz = vbv[2];
        float Cx = vcv[0], Cy = vcv[1], Cz = vcv[2];

        float abx = Bx - Ax, aby = By - Ay, abz = Bz - Az;
        float acx = Cx - Ax, acy = Cy - Ay, acz = Cz - Az;
        float bcx = Cx - Bx, bcy = Cy - By, bcz = Cz - Bz;

        float qaa = abx * abx + aby * aby + abz * abz;
        float qab = abx * acx + aby * acy + abz * acz;
        float qac = acx * acx + acy * acy + acz * acz;
        float qbc = bcx * bcx + bcy * bcy + bcz * bcz;

        float nx = aby * acz - abz * acy;
        float ny = abz * acx - abx * acz;
        float nz = abx * acy - aby * acx;
        float gram = nx * nx + ny * ny + nz * nz;
        float inv_n = rsqrtf(fmaxf(gram, EPSF));

        float ivb = (qac * abz - qab * acz) * dz;
        float ivc = (qaa * acz - qab * abz) * dz;
        float iva = -ivb - ivc;
        float ihs = nz * dz * inv_n;

        tc[10 * f + 0] = make_float4(abx, aby, abz, __fdividef(1.0f, fmaxf(qaa, EPSF)));
        tc[10 * f + 1] = make_float4(acx, acy, acz, __fdividef(1.0f, fmaxf(qac, EPSF)));
        tc[10 * f + 2] = make_float4(bcx, bcy, bcz, __fdividef(1.0f, fmaxf(qbc, EPSF)));
        tc[10 * f + 3] = make_float4(Ax, Ay, Az, qaa - qab);  // kbc
        tc[10 * f + 4] = make_float4(Bx, By, Bz, inv_n);
        tc[10 * f + 5] = make_float4(Cx, Cy, Cz, gram);
        tc[10 * f + 6] = make_float4(nx, ny, nz, qab);
        tc[10 * f + 7] = make_float4(qaa, qac, ivb, ivc);
        tc[10 * f + 8] = make_float4(abz * dz, acz * dz, ihs, iva);
        // 1/0 = inf is fine: lin_interval never uses kl when step == 0
        tc[10 * f + 9] = make_float4(1.0f / ivb, 1.0f / ivc, 1.0f / iva, 0.0f);
    }
    __syncthreads();

    const int g  = blockIdx.x * THREADS + threadIdx.x;    // [0, 1024)
    const int ix = g >> 5;
    const int iy = g & 31;

    const float px  = ((float)ix + 0.5f) * dz;
    const float py  = ((float)iy + 0.5f) * dz;
    const float pz0 = 0.5f * dz;
    const int pbase = (ix * 32 + iy) * 32;

    float md[KPT];
    #pragma unroll
    for (int k = 0; k < KPT; ++k) md[k] = INF_F;
    unsigned par = 0u;

    for (int f = 0; f < ntri; ++f) {
        const float4 c0 = tc[10 * f + 0];
        const float4 c1 = tc[10 * f + 1];
        const float4 c2 = tc[10 * f + 2];
        const float4 c3 = tc[10 * f + 3];
        const float4 c4 = tc[10 * f + 4];
        const float4 c5 = tc[10 * f + 5];
        const float4 c6 = tc[10 * f + 6];
        const float4 c7 = tc[10 * f + 7];
        const float4 c8 = tc[10 * f + 8];
        const float4 c9 = tc[10 * f + 9];
        const float qaa = c7.x, qac = c7.y, qab = c6.w, gram = c5.w;

        // ---- ray crossing (den == nz), fully hoisted ----
        {
            float cpx2 = px - c5.x, cpy2 = py - c5.y;
            float nz = c6.z;
            float e0 = c4.y - c5.y;
            float e1 = c5.x - c4.x;
            float un = e0 * cpx2 + e1 * cpy2;
            float vn = (c5.y - c3.y) * cpx2 + (c3.x - c5.x) * cpy2;
            float wn = nz - un - vn;
            bool c2d = (fabsf(nz) >= EPSF)
                     & (un * nz >= 0.0f) & (vn * nz >= 0.0f) & (wn * nz >= 0.0f);
            if (c2d) {
                float zhit = __fdividef(un * c3.z + vn * c4.z + wn * c5.z, nz);
                float fcnt = (zhit - pz0) * (float)G_DIM;
                int n = (int)ceilf(fminf(fmaxf(fcnt, 0.0f), (float)KPT));
                par ^= (n >= 32) ? 0xFFFFFFFFu : ((1u << n) - 1u);
            }
        }

        // ---- per-pair setup ----
        const float apx = px - c3.x, apy = py - c3.y;
        const float bpx = px - c4.x, bpy = py - c4.y;
        float apz = pz0 - c3.z;
        float bpz = pz0 - c4.z;
        float d1 = c0.x * apx + c0.y * apy + c0.z * apz;
        float d2 = c1.x * apx + c1.y * apy + c1.z * apz;
        float d43 = (d2 - d1) + c3.w;
        float hs = (c6.x * apx + c6.y * apy + c6.z * apz) * c4.w;
        const float iab = c8.x, iac = c8.y, i43 = iac - iab, ihs = c8.z;

        // interior k-interval from vb, vc, va (all affine in k)
        unsigned imask;
        {
            float vb0 = qac * d1 - qab * d2;
            float vc0 = qaa * d2 - qab * d1;
            float va0 = gram - vb0 - vc0;
            float lob, hib, loc, hic, loa, hia;
            lin_interval(vb0, c7.z, c9.x, lob, hib);
            lin_interval(vc0, c7.w, c9.y, loc, hic);
            lin_interval(va0, c8.w, c9.z, loa, hia);
            float lo = fmaxf(fmaxf(lob, loc), loa);
            float hi = fminf(fminf(hib, hic), hia);
            int ilo = (int)ceilf(fminf(fmaxf(lo, 0.0f), 33.0f));
            int ihi = (int)ceilf(fminf(fmaxf(hi, 0.0f), 32.0f));
            unsigned long long below_hi = (1ull << ihi) - 1ull;
            unsigned long long below_lo = (1ull << ilo) - 1ull;
            imask = (unsigned)(below_hi & ~below_lo);
        }

        #pragma unroll
        for (int k = 0; k < KPT; ++k) {
            float t1 = __saturatef(d1 * c0.w);
            float rx = apx - t1 * c0.x;
            float ry = apy - t1 * c0.y;
            float rz = apz - t1 * c0.z;
            float dAB = rx * rx + ry * ry + rz * rz;
            float t2 = __saturatef(d2 * c1.w);
            rx = apx - t2 * c1.x;
            ry = apy - t2 * c1.y;
            rz = apz - t2 * c1.z;
            float dAC = rx * rx + ry * ry + rz * rz;
            float t3 = __saturatef(d43 * c2.w);
            rx = bpx - t3 * c2.x;
            ry = bpy - t3 * c2.y;
            rz = bpz - t3 * c2.z;
            float dBC = rx * rx + ry * ry + rz * rz;

            float m = fminf(fminf(dAB, dAC), dBC);

            float hh = hs * hs;
            if ((imask >> k) & 1u) m = hh;

            md[k] = fminf(md[k], m);

            d1 += iab; d2 += iac; d43 += i43;
            apz += dz; bpz += dz; hs += ihs;
        }
    }

    #pragma unroll
    for (int k = 0; k < KPT; ++k)
        atomicMin(&g_md2min[pbase + k], __float_as_uint(md[k]));
    if (par) atomicXor(&g_parity[g], par);
}

__global__ void __launch_bounds__(256)
sdf_finalize(float* __restrict__ out)
{
    int p = blockIdx.x * 256 + threadIdx.x;               // [0, 32768)
    float m = __uint_as_float(g_md2min[p]);
    unsigned par = (g_parity[p >> 5] >> (p & 31)) & 1u;
    out[p] = par ? sqrtf(m) : 0.0f;
}

extern "C" void kernel_launch(void* const* d_in, const int* in_sizes, int n_in,
                              void* d_out, int out_size)
{
    const int* faces = nullptr;
    const float* verts = nullptr;
    for (int i = 0; i < n_in; ++i) {
        if (in_sizes[i] == 3 * N_FACES)   faces = (const int*)d_in[i];
        else if (in_sizes[i] == 3 * 1026) verts = (const float*)d_in[i];
    }
    if (!faces) faces = (const int*)d_in[0];
    if (!verts) verts = (const float*)d_in[1];

    sdf_init<<<N_PTS / 256, 256>>>();
    dim3 grid(N_GROUPS / THREADS, N_CHUNKS);              // 8 x 74 = 592 blocks
    sdf_main<<<grid, THREADS>>>(faces, verts);
    sdf_finalize<<<N_PTS / 256, 256>>>((float*)d_out);
}

// round 15
// speedup vs baseline: 1.4831x; 1.1886x over previous
#include <cuda_runtime.h>
#include <math.h>

// SDF2: mesh -> voxel (inside ? distance : 0) grid. Round-15:
//   ORTHO-FRAME formulation: per triangle build unit frame (per-edge ê, m̂=ŵ×ê,
//   shared ŵ=n̂). Maintain 7 affine-in-z coords: q_e=(p-V0)·ê, s_e=(p-V0)·m̂,
//   pw=(p-A)·ŵ. Exact distances as sums of squares of SMALL affine coords
//   (no large-number cancellation):
//     segment: d_e² = (q-clamp(q,0,L))² + s_e²;  dist² = pw² + min_e d_e²
//     inside (all s_e>0, interval-in-k, gated off for degenerate): dist² = pw²
//   17 fma-ops/k vs round-11's 28. Degenerate faces: ŵ ⊥ longest edge,
//   zero edges get arbitrary unit ê ⊥ ŵ (orthonormal triad => exact vertex
//   distance), inside-mask forced empty.
//   Skeleton: KPT=32, 74 balanced chunks (592 blocks = 148x4), hoisted parity,
//   RED-atomic reduce (atomicMin float bits), round-11 finalize.

#define G_DIM    32
#define N_PTS    (G_DIM * G_DIM * G_DIM)          // 32768
#define N_FACES  2048
#define N_CHUNKS 74
#define TRI_MAX  28
#define KPT      32
#define N_GROUPS (N_PTS / KPT)                    // 1024
#define THREADS  128
#define EPSF     1e-12f
#define INF_F    __int_as_float(0x7F800000)

__device__ unsigned g_md2min[N_PTS];              // float bits, monotone (md2>=0)
__device__ unsigned g_parity[N_GROUPS];           // 32 parity bits per word

__global__ void __launch_bounds__(256)
sdf_init()
{
    int i = blockIdx.x * 256 + threadIdx.x;
    if (i < N_PTS)    g_md2min[i] = 0x7F800000u;  // +inf
    if (i < N_GROUPS) g_parity[i] = 0u;
}

// interval of k where L0 + k*i > 0 (strict); inv_i = 1/i (inf ok when i==0)
__device__ __forceinline__ void lin_interval(float L0, float i, float inv_i,
                                             float& lo, float& hi)
{
    float kl = -L0 * inv_i;
    if (i > 0.0f)      { lo = kl;     hi = INF_F; }
    else if (i < 0.0f) { lo = -INF_F; hi = kl; }
    else               { lo = (L0 > 0.0f) ? -INF_F : INF_F;
                         hi = (L0 > 0.0f) ?  INF_F : -INF_F; }
}

__global__ void __launch_bounds__(THREADS, 4)
sdf_main(const int* __restrict__ faces, const float* __restrict__ verts)
{
    // 12 float4 per triangle:
    // 0: ê1.xyz, L1   1: ê2.xyz, L2   2: ê3.xyz, L3      (edges AB, BC, CA)
    // 3: m1.xyz, is1  4: m2.xyz, is2  5: m3.xyz, is3
    // 6: ŵ.xyz, ipw   7: A.xyz, nz    8: B.xyz, nondeg   9: C.xyz, 0
    // 10: iq1, iq2, iq3, 0            11: inv_is1, inv_is2, inv_is3, 0
    __shared__ float4 tc[12 * TRI_MAX];           // 5.4 KB

    const int start = (blockIdx.y * N_FACES) / N_CHUNKS;
    const int end   = ((blockIdx.y + 1) * N_FACES) / N_CHUNKS;
    const int ntri  = end - start;
    const float dz  = 1.0f / (float)G_DIM;

    if (threadIdx.x < ntri) {
        const int f = threadIdx.x;
        const int base = (start + f) * 3;
        const float* va  = verts + 3 * faces[base + 0];
        const float* vbv = verts + 3 * faces[base + 1];
        const float* vcv = verts + 3 * faces[base + 2];
        float Ax = va[0],  Ay = va[1],  Az = va[2];
        float Bx = vbv[0], By = vbv[1], Bz = vbv[2];
        float Cx = vcv[0], Cy = vcv[1], Cz = vcv[2];

        // cyclic edges: E1 = A->B, E2 = B->C, E3 = C->A
        float e1x = Bx-Ax, e1y = By-Ay, e1z = Bz-Az;
        float e2x = Cx-Bx, e2y = Cy-By, e2z = Cz-Bz;
        float e3x = Ax-Cx, e3y = Ay-Cy, e3z = Az-Cz;
        float L1 = sqrtf(e1x*e1x + e1y*e1y + e1z*e1z);
        float L2 = sqrtf(e2x*e2x + e2y*e2y + e2z*e2z);
        float L3 = sqrtf(e3x*e3x + e3y*e3y + e3z*e3z);

        float acx = Cx-Ax, acy = Cy-Ay, acz = Cz-Az;
        float nx = e1y*acz - e1z*acy;
        float ny = e1z*acx - e1x*acz;
        float nz = e1x*acy - e1y*acx;
        float gram = nx*nx + ny*ny + nz*nz;
        bool nondeg = gram > 1e-12f;

        float wx, wy, wz;
        if (nondeg) {
            float inv_n = rsqrtf(gram);
            wx = nx*inv_n; wy = ny*inv_n; wz = nz*inv_n;
        } else {
            // w perpendicular to longest nonzero edge (or arbitrary)
            float bx2 = 1.0f, by2 = 0.0f, bz2 = 0.0f;
            if      (L1 > 0.0f) { float r = 1.0f/L1; bx2 = e1x*r; by2 = e1y*r; bz2 = e1z*r; }
            else if (L2 > 0.0f) { float r = 1.0f/L2; bx2 = e2x*r; by2 = e2y*r; bz2 = e2z*r; }
            else if (L3 > 0.0f) { float r = 1.0f/L3; bx2 = e3x*r; by2 = e3y*r; bz2 = e3z*r; }
            float px_ = (fabsf(bx2) < 0.9f) ? 1.0f : 0.0f;
            float py_ = 1.0f - px_;
            // w = normalize(b x pick)
            float cx2 = by2*0.0f - bz2*py_;
            float cy2 = bz2*px_ - bx2*0.0f;
            float cz2 = bx2*py_ - by2*px_;
            float rn = rsqrtf(fmaxf(cx2*cx2 + cy2*cy2 + cz2*cz2, EPSF));
            wx = cx2*rn; wy = cy2*rn; wz = cz2*rn;
        }
        // u0: arbitrary unit perpendicular to w (for zero-length edges)
        float u0x, u0y, u0z;
        {
            float px_ = (fabsf(wx) < 0.9f) ? 1.0f : 0.0f;
            float py_ = 1.0f - px_;
            float cx2 = wy*0.0f - wz*py_;
            float cy2 = wz*px_ - wx*0.0f;
            float cz2 = wx*py_ - wy*px_;
            float rn = rsqrtf(fmaxf(cx2*cx2 + cy2*cy2 + cz2*cz2, EPSF));
            u0x = cx2*rn; u0y = cy2*rn; u0z = cz2*rn;
        }

        float h1x, h1y, h1z, h2x, h2y, h2z, h3x, h3y, h3z;
        if (L1 > 0.0f) { float r = 1.0f/L1; h1x = e1x*r; h1y = e1y*r; h1z = e1z*r; }
        else           { h1x = u0x; h1y = u0y; h1z = u0z; }
        if (L2 > 0.0f) { float r = 1.0f/L2; h2x = e2x*r; h2y = e2y*r; h2z = e2z*r; }
        else           { h2x = u0x; h2y = u0y; h2z = u0z; }
        if (L3 > 0.0f) { float r = 1.0f/L3; h3x = e3x*r; h3y = e3y*r; h3z = e3z*r; }
        else           { h3x = u0x; h3y = u0y; h3z = u0z; }

        // m_i = w x ê_i, flipped so the opposite vertex has s > 0
        float m1x = wy*h1z - wz*h1y, m1y = wz*h1x - wx*h1z, m1z = wx*h1y - wy*h1x;
        float m2x = wy*h2z - wz*h2y, m2y = wz*h2x - wx*h2z, m2z = wx*h2y - wy*h2x;
        float m3x = wy*h3z - wz*h3y, m3y = wz*h3x - wx*h3z, m3z = wx*h3y - wy*h3x;
        float sC = (Cx-Ax)*m1x + (Cy-Ay)*m1y + (Cz-Az)*m1z;
        if (sC < 0.0f) { m1x = -m1x; m1y = -m1y; m1z = -m1z; }
        float sA = (Ax-Bx)*m2x + (Ay-By)*m2y + (Az-Bz)*m2z;
        if (sA < 0.0f) { m2x = -m2x; m2y = -m2y; m2z = -m2z; }
        float sB = (Bx-Cx)*m3x + (By-Cy)*m3y + (Bz-Cz)*m3z;
        if (sB < 0.0f) { m3x = -m3x; m3y = -m3y; m3z = -m3z; }

        float is1 = m1z*dz, is2 = m2z*dz, is3 = m3z*dz;

        tc[12*f + 0]  = make_float4(h1x, h1y, h1z, L1);
        tc[12*f + 1]  = make_float4(h2x, h2y, h2z, L2);
        tc[12*f + 2]  = make_float4(h3x, h3y, h3z, L3);
        tc[12*f + 3]  = make_float4(m1x, m1y, m1z, is1);
        tc[12*f + 4]  = make_float4(m2x, m2y, m2z, is2);
        tc[12*f + 5]  = make_float4(m3x, m3y, m3z, is3);
        tc[12*f + 6]  = make_float4(wx, wy, wz, wz*dz);
        tc[12*f + 7]  = make_float4(Ax, Ay, Az, nz);
        tc[12*f + 8]  = make_float4(Bx, By, Bz, nondeg ? 1.0f : 0.0f);
        tc[12*f + 9]  = make_float4(Cx, Cy, Cz, 0.0f);
        tc[12*f + 10] = make_float4(h1z*dz, h2z*dz, h3z*dz, 0.0f);
        tc[12*f + 11] = make_float4(1.0f/is1, 1.0f/is2, 1.0f/is3, 0.0f);
    }
    __syncthreads();

    const int g  = blockIdx.x * THREADS + threadIdx.x;    // [0, 1024)
    const int ix = g >> 5;
    const int iy = g & 31;

    const float px  = ((float)ix + 0.5f) * dz;
    const float py  = ((float)iy + 0.5f) * dz;
    const float pz0 = 0.5f * dz;
    const int pbase = (ix * 32 + iy) * 32;

    float md[KPT];
    #pragma unroll
    for (int k = 0; k < KPT; ++k) md[k] = INF_F;
    unsigned par = 0u;

    for (int f = 0; f < ntri; ++f) {
        const float4 c0  = tc[12*f + 0];
        const float4 c1  = tc[12*f + 1];
        const float4 c2  = tc[12*f + 2];
        const float4 c3  = tc[12*f + 3];
        const float4 c4  = tc[12*f + 4];
        const float4 c5  = tc[12*f + 5];
        const float4 c6  = tc[12*f + 6];
        const float4 c7  = tc[12*f + 7];
        const float4 c8  = tc[12*f + 8];
        const float4 c9  = tc[12*f + 9];
        const float4 c10 = tc[12*f + 10];
        const float4 c11 = tc[12*f + 11];
        const float L1 = c0.w, L2 = c1.w, L3 = c2.w;

        // ---- ray crossing (den == nz), fully hoisted ----
        {
            float cpx2 = px - c9.x, cpy2 = py - c9.y;
            float nz = c7.w;
            float e0 = c8.y - c9.y;                       // By - Cy
            float e1 = c9.x - c8.x;                       // Cx - Bx
            float un = e0 * cpx2 + e1 * cpy2;
            float vn = (c9.y - c7.y) * cpx2 + (c7.x - c9.x) * cpy2;
            float wn = nz - un - vn;
            bool c2d = (fabsf(nz) >= EPSF)
                     & (un * nz >= 0.0f) & (vn * nz >= 0.0f) & (wn * nz >= 0.0f);
            if (c2d) {
                float zhit = __fdividef(un * c7.z + vn * c8.z + wn * c9.z, nz);
                float fcnt = (zhit - pz0) * (float)G_DIM;
                int n = (int)ceilf(fminf(fmaxf(fcnt, 0.0f), (float)KPT));
                par ^= (n >= 32) ? 0xFFFFFFFFu : ((1u << n) - 1u);
            }
        }

        // ---- per-pair frame-coordinate init (7 dots) ----
        const float apx = px - c7.x, apy = py - c7.y; float apz = pz0 - c7.z;
        const float bpx = px - c8.x, bpy = py - c8.y; float bpz = pz0 - c8.z;
        const float cpx = px - c9.x, cpy = py - c9.y; float cpz = pz0 - c9.z;
        float q1 = apx*c0.x + apy*c0.y + apz*c0.z;
        float s1 = apx*c3.x + apy*c3.y + apz*c3.z;
        float q2 = bpx*c1.x + bpy*c1.y + bpz*c1.z;
        float s2 = bpx*c4.x + bpy*c4.y + bpz*c4.z;
        float q3 = cpx*c2.x + cpy*c2.y + cpz*c2.z;
        float s3 = cpx*c5.x + cpy*c5.y + cpz*c5.z;
        float pw = apx*c6.x + apy*c6.y + apz*c6.z;
        const float iq1 = c10.x, iq2 = c10.y, iq3 = c10.z;
        const float is1 = c3.w,  is2 = c4.w,  is3 = c5.w, ipw = c6.w;

        // inside interval (all s_e > 0), gated off for degenerate faces
        unsigned imask = 0u;
        if (c8.w != 0.0f) {
            float lo1, hi1, lo2, hi2, lo3, hi3;
            lin_interval(s1, is1, c11.x, lo1, hi1);
            lin_interval(s2, is2, c11.y, lo2, hi2);
            lin_interval(s3, is3, c11.z, lo3, hi3);
            float lo = fmaxf(fmaxf(lo1, lo2), lo3);
            float hi = fminf(fminf(hi1, hi2), hi3);
            int ilo = (int)ceilf(fminf(fmaxf(lo, 0.0f), 33.0f));
            int ihi = (int)ceilf(fminf(fmaxf(hi, 0.0f), 32.0f));
            unsigned long long below_hi = (1ull << ihi) - 1ull;
            unsigned long long below_lo = (1ull << ilo) - 1ull;
            imask = (unsigned)(below_hi & ~below_lo);
        }

        #pragma unroll
        for (int k = 0; k < KPT; ++k) {
            float w1 = q1 - fminf(fmaxf(q1, 0.0f), L1);
            float w2 = q2 - fminf(fmaxf(q2, 0.0f), L2);
            float w3 = q3 - fminf(fmaxf(q3, 0.0f), L3);
            float d1e = fmaf(w1, w1, s1 * s1);
            float d2e = fmaf(w2, w2, s2 * s2);
            float d3e = fmaf(w3, w3, s3 * s3);
            float d2d = fminf(fminf(d1e, d2e), d3e);
            if ((imask >> k) & 1u) d2d = 0.0f;
            float dist = fmaf(pw, pw, d2d);
            md[k] = fminf(md[k], dist);

            q1 += iq1; q2 += iq2; q3 += iq3;
            s1 += is1; s2 += is2; s3 += is3; pw += ipw;
        }
    }

    #pragma unroll
    for (int k = 0; k < KPT; ++k)
        atomicMin(&g_md2min[pbase + k], __float_as_uint(md[k]));
    if (par) atomicXor(&g_parity[g], par);
}

__global__ void __launch_bounds__(256)
sdf_finalize(float* __restrict__ out)
{
    int p = blockIdx.x * 256 + threadIdx.x;               // [0, 32768)
    float m = __uint_as_float(g_md2min[p]);
    unsigned par = (g_parity[p >> 5] >> (p & 31)) & 1u;
    out[p] = par ? sqrtf(m) : 0.0f;
}

extern "C" void kernel_launch(void* const* d_in, const int* in_sizes, int n_in,
                              void* d_out, int out_size)
{
    const int* faces = nullptr;
    const float* verts = nullptr;
    for (int i = 0; i < n_in; ++i) {
        if (in_sizes[i] == 3 * N_FACES)   faces = (const int*)d_in[i];
        else if (in_sizes[i] == 3 * 1026) verts = (const float*)d_in[i];
    }
    if (!faces) faces = (const int*)d_in[0];
    if (!verts) verts = (const float*)d_in[1];

    sdf_init<<<N_PTS / 256, 256>>>();
    dim3 grid(N_GROUPS / THREADS, N_CHUNKS);              // 8 x 74 = 592 blocks
    sdf_main<<<grid, THREADS>>>(faces, verts);
    sdf_finalize<<<N_PTS / 256, 256>>>((float*)d_out);
}